// round 12
// baseline (speedup 1.0000x reference)
#include <cuda_runtime.h>
#include <cuda_fp16.h>
#include <cstdint>

// Problem constants
#define NN  50000
#define EE  1600000
#define DD  128
#define RR  8
#define NR  (NN*RR)      // 400000
#define KT  1152         // R*D + D
#define NPAD 50048       // 391 * 128
#define LN_EPS 1e-5f
#define NCH 72           // KT / 16
#define CAP 32           // fixed bucket capacity (P(overflow) ~ 4e-12)

// Scratch (device globals — allocation is forbidden). .bss zero-init.
__device__ __align__(256) unsigned short g_wt[128 * KT];   // fp16 W^T [N=128,K]
__device__ __align__(256) unsigned short g_x16[NN * DD];   // fp16 copy of x
__device__ int g_cnt[NR];
__device__ unsigned short g_srt[(size_t)NR * CAP];         // 25.6 MB bucket slots (u16 src ids)
__device__ int g_ei64, g_et64;

// ---------------------------------------------------------------------------
static __device__ __forceinline__ uint32_t smem_u32(const void* p) {
    uint32_t a;
    asm("{ .reg .u64 t; cvta.to.shared.u64 t, %1; cvt.u32.u64 %0, t; }"
        : "=r"(a) : "l"(p));
    return a;
}
static __device__ __forceinline__ void cp16(uint32_t dst, const void* src) {
    asm volatile("cp.async.cg.shared.global [%0], [%1], 16;"
                 :: "r"(dst), "l"(src) : "memory");
}
static __device__ __forceinline__ uint32_t h2u(__half2 h) {
    return *(uint32_t*)&h;
}
static __device__ __forceinline__ void mma_f16(float c[4], const uint32_t a[4],
                                               const uint32_t b[2]) {
    asm volatile(
        "mma.sync.aligned.m16n8k16.row.col.f32.f16.f16.f32 "
        "{%0,%1,%2,%3}, {%4,%5,%6,%7}, {%8,%9}, {%0,%1,%2,%3};"
        : "+f"(c[0]), "+f"(c[1]), "+f"(c[2]), "+f"(c[3])
        : "r"(a[0]), "r"(a[1]), "r"(a[2]), "r"(a[3]), "r"(b[0]), "r"(b[1]));
}

// ---------------------------------------------------------------------------
// k_init: zero counts + dtype detect (block 0) + fp16 x copy + fp16 W^T.
// ---------------------------------------------------------------------------
__global__ void k_init(const unsigned int* __restrict__ ei_w,
                       const unsigned int* __restrict__ et_w,
                       const float* __restrict__ x,
                       const float* __restrict__ Wrel,
                       const float* __restrict__ Wroot) {
    int i = blockIdx.x * blockDim.x + threadIdx.x;

    if (blockIdx.x == 0) {                       // dtype detection
        __shared__ unsigned int a_ei, a_et;
        if (threadIdx.x == 0) { a_ei = 0u; a_et = 0u; }
        __syncthreads();
        unsigned int vei = 0u, vet = 0u;
#pragma unroll
        for (int j = 0; j < 8; j++) {
            int idx = threadIdx.x * 8 + j;
            vei |= ei_w[2 * idx + 1];
            vet |= et_w[2 * idx + 1];
        }
        atomicOr(&a_ei, vei);
        atomicOr(&a_et, vet);
        __syncthreads();
        if (threadIdx.x == 0) {
            g_ei64 = (a_ei == 0u) ? 1 : 0;
            g_et64 = (a_et == 0u) ? 1 : 0;
        }
    }
    if (i < NR) g_cnt[i] = 0;
    if (i < NN * 32) {                           // x -> fp16
        int node = i >> 5, c = (i & 31) * 4;
        float4 v = *(const float4*)(x + (size_t)node * DD + c);
        uint32_t u0 = h2u(__floats2half2_rn(v.x, v.y));
        uint32_t u1 = h2u(__floats2half2_rn(v.z, v.w));
        ((uint2*)g_x16)[i] = make_uint2(u0, u1);
    }
    if (i < 128 * KT) {                          // W^T fp16
        int n = i & 127, k = i >> 7;
        float v = (k < 1024) ? Wrel[(size_t)k * 128 + n]
                             : Wroot[(size_t)(k - 1024) * 128 + n];
        g_wt[(size_t)n * KT + k] = __half_as_ushort(__float2half_rn(v));
    }
}

// ---------------------------------------------------------------------------
// k_sort: one pass over edges -> fixed-capacity buckets (u16 src ids).
// ---------------------------------------------------------------------------
__global__ void k_sort(const void* __restrict__ ei_v,
                       const void* __restrict__ et_v) {
    int e = blockIdx.x * blockDim.x + threadIdx.x;
    if (e >= EE) return;
    int s, d, r;
    if (g_ei64) {
        const long long* p = (const long long*)ei_v;
        s = (int)p[e];
        d = (int)p[EE + e];
    } else {
        const int* p = (const int*)ei_v;
        s = p[e];
        d = p[EE + e];
    }
    if (g_et64) r = (int)((const long long*)et_v)[e];
    else        r = ((const int*)et_v)[e];
    int key = d * RR + r;
    int pos = atomicAdd(&g_cnt[key], 1);
    if (pos < CAP) g_srt[(size_t)key * CAP + pos] = (unsigned short)s;
}

// ---------------------------------------------------------------------------
// FUSED: gather + fp16 mma GEMM (M=128/CTA, N=128, K=1152) + bias + LN + ReLU.
// A-chunks built on the fly: per relation r, bucket src-lists cached in smem;
// each thread-pair averages its node's x16 rows for the 16-half K-slice.
// Root chunks (ch>=64) read x16 directly. B: proven 4-stage cp.async.
// 8 warps 4x2, warp tile 32x64 (the measured-best geometry).
// ---------------------------------------------------------------------------
__global__ void __launch_bounds__(256, 2)
k_fused(const float* __restrict__ bias, const float* __restrict__ gamma,
        const float* __restrict__ beta, float* __restrict__ out) {
    __shared__ unsigned short sA[2][128 * 24];     // 12.3 KB (double-buffered)
    __shared__ unsigned short sB[4][128 * 24];     // 24.6 KB
    __shared__ unsigned short sSrc[CAP][128];      // 8 KB (aliased by sRow post-loop)
    __shared__ int sCnt[128];
    __shared__ float s_bias[128], s_g[128], s_b[128];

    const int tid = threadIdx.x;
    const int wid = tid >> 5, lane = tid & 31;
    const int grp = lane >> 2, tig = lane & 3;
    const int wm = wid & 3, wn = wid >> 2;
    const int tileM = blockIdx.x * 128;
    const int rBase = wm * 32;
    const int cBase = wn * 64;

    if (tid < 128) { s_bias[tid] = bias[tid]; s_g[tid] = gamma[tid]; s_b[tid] = beta[tid]; }

    float c[2][8][4];
#pragma unroll
    for (int mi = 0; mi < 2; mi++)
#pragma unroll
        for (int ni = 0; ni < 8; ni++)
#pragma unroll
            for (int j = 0; j < 4; j++) c[mi][ni][j] = 0.f;

    const int mB = tid >> 1, pB = (tid & 1) * 8;   // B prefetch slot
    const int gm = tid >> 1, hs = tid & 1;         // gather: node row, half-sel

#define PREFB(CH)                                                              \
    {                                                                          \
        int ch_ = (CH);                                                        \
        if (ch_ < NCH)                                                         \
            cp16(smem_u32(&sB[ch_ & 3][mB * 24 + pB]),                         \
                 g_wt + (size_t)mB * KT + ch_ * 16 + pB);                      \
        asm volatile("cp.async.commit_group;" ::: "memory");                   \
    }

    PREFB(0); PREFB(1); PREFB(2);

    for (int ch = 0; ch < NCH; ch++) {
        const int r = ch >> 3, ksub = ch & 7;
        const int abuf = ch & 1, bbuf = ch & 3;

        // --- relation boundary: cache bucket lists for r (u16 src ids) ---
        if (ksub == 0 && r < 8) {
            if (tid < 128) {
                int node = tileM + tid;
                int n = 0;
                if (node < NN) {
                    n = min(g_cnt[node * RR + r], CAP);
                    const unsigned short* bkt = g_srt + (size_t)(node * RR + r) * CAP;
                    for (int j = 0; j < n; j += 8) {
                        uint4 v = *(const uint4*)(bkt + j);
                        const unsigned short* sv = (const unsigned short*)&v;
#pragma unroll
                        for (int q = 0; q < 8; q++)
                            if (j + q < n) sSrc[j + q][tid] = sv[q];
                    }
                }
                sCnt[tid] = n;
            }
            __syncthreads();
        }

        // --- build sA[abuf]: 16-half K-slice for each of 128 nodes ---
        {
            uint4 st = make_uint4(0u, 0u, 0u, 0u);
            if (r < 8) {
                float2 ac0 = make_float2(0.f, 0.f), ac1 = ac0, ac2 = ac0, ac3 = ac0;
                int n = sCnt[gm];
                for (int j = 0; j < n; j++) {
                    int src = sSrc[j][gm];
                    uint4 u = *(const uint4*)(g_x16 + (size_t)src * DD + ksub * 16 + hs * 8);
                    const __half2* h = (const __half2*)&u;
                    float2 f0 = __half22float2(h[0]), f1 = __half22float2(h[1]);
                    float2 f2 = __half22float2(h[2]), f3 = __half22float2(h[3]);
                    ac0.x += f0.x; ac0.y += f0.y; ac1.x += f1.x; ac1.y += f1.y;
                    ac2.x += f2.x; ac2.y += f2.y; ac3.x += f3.x; ac3.y += f3.y;
                }
                float sc = 1.0f / fmaxf((float)n, 1.0f);
                st.x = h2u(__floats2half2_rn(ac0.x * sc, ac0.y * sc));
                st.y = h2u(__floats2half2_rn(ac1.x * sc, ac1.y * sc));
                st.z = h2u(__floats2half2_rn(ac2.x * sc, ac2.y * sc));
                st.w = h2u(__floats2half2_rn(ac3.x * sc, ac3.y * sc));
            } else {                                 // root: identity copy of x16
                int node = tileM + gm;
                if (node < NN)
                    st = *(const uint4*)(g_x16 + (size_t)node * DD + ksub * 16 + hs * 8);
            }
            *(uint4*)(&sA[abuf][gm * 24 + hs * 8]) = st;
        }

        asm volatile("cp.async.wait_group 2;" ::: "memory");
        __syncthreads();
        PREFB(ch + 3);

        // --- frag loads + 16 MMAs (identical to measured-best config) ---
        uint32_t a[2][4];
#pragma unroll
        for (int mi = 0; mi < 2; mi++) {
            const unsigned short* pa = &sA[abuf][(rBase + mi * 16 + grp) * 24 + tig * 2];
            a[mi][0] = *(const uint32_t*)pa;
            a[mi][1] = *(const uint32_t*)(pa + 8 * 24);
            a[mi][2] = *(const uint32_t*)(pa + 8);
            a[mi][3] = *(const uint32_t*)(pa + 8 * 24 + 8);
        }
        uint32_t b[8][2];
#pragma unroll
        for (int ni = 0; ni < 8; ni++) {
            const unsigned short* pb = &sB[bbuf][(cBase + ni * 8 + grp) * 24 + tig * 2];
            b[ni][0] = *(const uint32_t*)pb;
            b[ni][1] = *(const uint32_t*)(pb + 8);
        }
#pragma unroll
        for (int mi = 0; mi < 2; mi++)
#pragma unroll
            for (int ni = 0; ni < 8; ni++)
                mma_f16(c[mi][ni], a[mi], b[ni]);
    }
#undef PREFB
    __syncthreads();

    // sRow aliases the (now dead) sSrc region
    float2* sRow = (float2*)&sSrc[0][0];             // [2][128]

    // ---- epilogue: bias, per-row LN stats, normalize, ReLU, store ----
#pragma unroll
    for (int ni = 0; ni < 8; ni++) {
        int col = cBase + ni * 8 + 2 * tig;
        float b0 = s_bias[col], b1 = s_bias[col + 1];
#pragma unroll
        for (int mi = 0; mi < 2; mi++) {
            c[mi][ni][0] += b0; c[mi][ni][1] += b1;
            c[mi][ni][2] += b0; c[mi][ni][3] += b1;
        }
    }
#pragma unroll
    for (int mi = 0; mi < 2; mi++)
#pragma unroll
        for (int h = 0; h < 2; h++) {
            float s = 0.f, ss = 0.f;
#pragma unroll
            for (int ni = 0; ni < 8; ni++) {
                float v0 = c[mi][ni][2 * h], v1 = c[mi][ni][2 * h + 1];
                s += v0 + v1;
                ss += v0 * v0 + v1 * v1;
            }
            s  += __shfl_xor_sync(0xffffffffu, s, 1);
            s  += __shfl_xor_sync(0xffffffffu, s, 2);
            ss += __shfl_xor_sync(0xffffffffu, ss, 1);
            ss += __shfl_xor_sync(0xffffffffu, ss, 2);
            if (tig == 0)
                sRow[wn * 128 + rBase + mi * 16 + h * 8 + grp] = make_float2(s, ss);
        }
    __syncthreads();

#pragma unroll
    for (int mi = 0; mi < 2; mi++)
#pragma unroll
        for (int h = 0; h < 2; h++) {
            int row = rBase + mi * 16 + h * 8 + grp;
            int gRow = tileM + row;
            if (gRow >= NN) continue;
            float2 p0v = sRow[row], p1v = sRow[128 + row];
            float s = p0v.x + p1v.x, ss = p0v.y + p1v.y;
            float mean = s * (1.0f / DD);
            float var  = ss * (1.0f / DD) - mean * mean;
            float rstd = rsqrtf(var + LN_EPS);
#pragma unroll
            for (int ni = 0; ni < 8; ni++) {
                int col = cBase + ni * 8 + 2 * tig;
                float2 rv;
                rv.x = fmaxf((c[mi][ni][2 * h]     - mean) * rstd * s_g[col]     + s_b[col],     0.f);
                rv.y = fmaxf((c[mi][ni][2 * h + 1] - mean) * rstd * s_g[col + 1] + s_b[col + 1], 0.f);
                *(float2*)(out + (size_t)gRow * DD + col) = rv;
            }
        }
}

// ---------------------------------------------------------------------------
extern "C" void kernel_launch(void* const* d_in, const int* in_sizes, int n_in,
                              void* d_out, int out_size) {
    const float* x  = (const float*)d_in[0];
    const void*  ei = d_in[1];
    const void*  et = d_in[2];
    int base = 3;
    if (n_in > 3 && in_sizes[3] == 1) base = 4;
    const float* Wrel  = (const float*)d_in[base + 0];
    const float* Wroot = (const float*)d_in[base + 1];
    const float* bias  = (const float*)d_in[base + 2];
    const float* gamma = (const float*)d_in[base + 3];
    const float* beta  = (const float*)d_in[base + 4];
    float* out = (float*)d_out;

    k_init <<<(NN * 32 + 255) / 256, 256>>>((const unsigned int*)ei,
                                            (const unsigned int*)et,
                                            x, Wrel, Wroot);
    k_sort <<<(EE + 255) / 256, 256>>>(ei, et);
    k_fused<<<NPAD / 128, 256>>>(bias, gamma, beta, out);
}

// round 13
// speedup vs baseline: 1.6847x; 1.6847x over previous
#include <cuda_runtime.h>
#include <cuda_fp16.h>
#include <cstdint>

// Problem constants
#define NN  50000
#define EE  1600000
#define DD  128
#define RR  8
#define NR  (NN*RR)      // 400000
#define KT  1152         // R*D + D
#define NPAD 50048       // 391 * 128
#define LN_EPS 1e-5f
#define NCH 36           // KT / 32
#define CAP 32           // fixed bucket capacity (P(overflow) ~ 4e-12)

// Scratch (device globals — allocation is forbidden). .bss zero-init.
__device__ __align__(256) unsigned short g_a[(size_t)NPAD * KT]; // 115 MB fp16 A
__device__ __align__(256) unsigned short g_wt[128 * KT];         // fp16 W^T [N=128,K]
__device__ __align__(256) unsigned short g_x16[NN * DD];         // fp16 copy of x
__device__ int g_cnt[NR];
__device__ unsigned short g_srt[(size_t)NR * CAP];               // 25.6 MB u16 bucket slots
__device__ int g_ei64, g_et64;

// ---------------------------------------------------------------------------
static __device__ __forceinline__ uint32_t smem_u32(const void* p) {
    uint32_t a;
    asm("{ .reg .u64 t; cvta.to.shared.u64 t, %1; cvt.u32.u64 %0, t; }"
        : "=r"(a) : "l"(p));
    return a;
}
static __device__ __forceinline__ void cp16(uint32_t dst, const void* src) {
    asm volatile("cp.async.cg.shared.global [%0], [%1], 16;"
                 :: "r"(dst), "l"(src) : "memory");
}
static __device__ __forceinline__ void st_cs_u2(void* p, uint32_t a, uint32_t b) {
    asm volatile("st.global.cs.v2.u32 [%0], {%1,%2};"
                 :: "l"(p), "r"(a), "r"(b) : "memory");
}
static __device__ __forceinline__ uint32_t h2u(__half2 h) {
    return *(uint32_t*)&h;
}
static __device__ __forceinline__ void mma_f16(float c[4], const uint32_t a[4],
                                               const uint32_t b[2]) {
    asm volatile(
        "mma.sync.aligned.m16n8k16.row.col.f32.f16.f16.f32 "
        "{%0,%1,%2,%3}, {%4,%5,%6,%7}, {%8,%9}, {%0,%1,%2,%3};"
        : "+f"(c[0]), "+f"(c[1]), "+f"(c[2]), "+f"(c[3])
        : "r"(a[0]), "r"(a[1]), "r"(a[2]), "r"(a[3]), "r"(b[0]), "r"(b[1]));
}

// ---------------------------------------------------------------------------
// k_init: zero counts + dtype detect (block 0) + fp16 x copy / A root slice +
// fp16 weight transpose.
// ---------------------------------------------------------------------------
__global__ void k_init(const unsigned int* __restrict__ ei_w,
                       const unsigned int* __restrict__ et_w,
                       const float* __restrict__ x,
                       const float* __restrict__ Wrel,
                       const float* __restrict__ Wroot) {
    int i = blockIdx.x * blockDim.x + threadIdx.x;

    if (blockIdx.x == 0) {                       // dtype detection
        __shared__ unsigned int a_ei, a_et;
        if (threadIdx.x == 0) { a_ei = 0u; a_et = 0u; }
        __syncthreads();
        unsigned int vei = 0u, vet = 0u;
#pragma unroll
        for (int j = 0; j < 8; j++) {
            int idx = threadIdx.x * 8 + j;
            vei |= ei_w[2 * idx + 1];
            vet |= et_w[2 * idx + 1];
        }
        atomicOr(&a_ei, vei);
        atomicOr(&a_et, vet);
        __syncthreads();
        if (threadIdx.x == 0) {
            g_ei64 = (a_ei == 0u) ? 1 : 0;
            g_et64 = (a_et == 0u) ? 1 : 0;
        }
    }
    if (i < NR) g_cnt[i] = 0;
    if (i < NN * 32) {                           // x -> fp16 + root slice of A
        int node = i >> 5, c = (i & 31) * 4;
        float4 v = *(const float4*)(x + (size_t)node * DD + c);
        uint32_t u0 = h2u(__floats2half2_rn(v.x, v.y));
        uint32_t u1 = h2u(__floats2half2_rn(v.z, v.w));
        ((uint2*)g_x16)[i] = make_uint2(u0, u1);
        st_cs_u2(g_a + (size_t)node * KT + 1024 + c, u0, u1);
    }
    if (i < 128 * KT) {                          // W^T fp16
        int n = i & 127, k = i >> 7;
        float v = (k < 1024) ? Wrel[(size_t)k * 128 + n]
                             : Wroot[(size_t)(k - 1024) * 128 + n];
        g_wt[(size_t)n * KT + k] = __half_as_ushort(__float2half_rn(v));
    }
}

// ---------------------------------------------------------------------------
// k_sort: one pass over edges -> fixed-capacity u16 buckets.
// ---------------------------------------------------------------------------
__global__ void k_sort(const void* __restrict__ ei_v,
                       const void* __restrict__ et_v) {
    int e = blockIdx.x * blockDim.x + threadIdx.x;
    if (e >= EE) return;
    int s, d, r;
    if (g_ei64) {
        const long long* p = (const long long*)ei_v;
        s = (int)p[e];
        d = (int)p[EE + e];
    } else {
        const int* p = (const int*)ei_v;
        s = p[e];
        d = p[EE + e];
    }
    if (g_et64) r = (int)((const long long*)et_v)[e];
    else        r = ((const int*)et_v)[e];
    int key = d * RR + r;
    int pos = atomicAdd(&g_cnt[key], 1);
    if (pos < CAP) g_srt[(size_t)key * CAP + pos] = (unsigned short)s;
}

// ---------------------------------------------------------------------------
// One warp per (dst,rel) bucket: A[node, rel*128..] = fp16(mean of x16[src])
// ---------------------------------------------------------------------------
__global__ __launch_bounds__(256)
void k_gather() {
    int w = (blockIdx.x * blockDim.x + threadIdx.x) >> 5;
    if (w >= NR) return;
    int lane = threadIdx.x & 31;
    const unsigned short* bucket = g_srt + (size_t)w * CAP;
    int n = min(g_cnt[w], CAP);
    const uint2* xv = (const uint2*)g_x16;
    float4 acc = make_float4(0.f, 0.f, 0.f, 0.f);
    int j = 0;
    for (; j + 3 < n; j += 4) {
        int s0 = bucket[j];
        int s1 = bucket[j + 1];
        int s2 = bucket[j + 2];
        int s3 = bucket[j + 3];
        uint2 u0 = xv[s0 * 32 + lane];
        uint2 u1 = xv[s1 * 32 + lane];
        uint2 u2 = xv[s2 * 32 + lane];
        uint2 u3 = xv[s3 * 32 + lane];
        float2 a0 = __half22float2(*(__half2*)&u0.x), b0 = __half22float2(*(__half2*)&u0.y);
        float2 a1 = __half22float2(*(__half2*)&u1.x), b1 = __half22float2(*(__half2*)&u1.y);
        float2 a2 = __half22float2(*(__half2*)&u2.x), b2 = __half22float2(*(__half2*)&u2.y);
        float2 a3 = __half22float2(*(__half2*)&u3.x), b3 = __half22float2(*(__half2*)&u3.y);
        acc.x += (a0.x + a1.x) + (a2.x + a3.x);
        acc.y += (a0.y + a1.y) + (a2.y + a3.y);
        acc.z += (b0.x + b1.x) + (b2.x + b3.x);
        acc.w += (b0.y + b1.y) + (b2.y + b3.y);
    }
    for (; j < n; j++) {
        int s0 = bucket[j];
        uint2 u0 = xv[s0 * 32 + lane];
        float2 a0 = __half22float2(*(__half2*)&u0.x), b0 = __half22float2(*(__half2*)&u0.y);
        acc.x += a0.x; acc.y += a0.y; acc.z += b0.x; acc.w += b0.y;
    }
    float sc = 1.0f / fmaxf((float)n, 1.0f);
    uint32_t u0 = h2u(__floats2half2_rn(acc.x * sc, acc.y * sc));
    uint32_t u1 = h2u(__floats2half2_rn(acc.z * sc, acc.w * sc));
    int node = w >> 3, rel = w & 7;
    st_cs_u2(g_a + (size_t)node * KT + rel * 128 + lane * 4, u0, u1);
}

// ---------------------------------------------------------------------------
// fp16 mma.sync GEMM (M=128/CTA, N=128, K=1152) + bias + LN + ReLU.
// 8 warps in 4x2; warp tile 32x64 via m16n8k16. BK=32 (36 chunks; half the
// sync boundaries of the BK=16 build). 4-stage cp.async, wait_group 2.
// Smem row stride 40 halves (pad 8) -> conflict-free frag LDS.
// ---------------------------------------------------------------------------
__global__ void __launch_bounds__(256, 2)
k_mma_ln(const float* __restrict__ bias, const float* __restrict__ gamma,
         const float* __restrict__ beta, float* __restrict__ out) {
    __shared__ unsigned short sA[4][128 * 40];   // 40.96 KB
    __shared__ unsigned short sB[4][128 * 40];   // 40.96 KB
    __shared__ float2 sRow[2][128];
    __shared__ float s_bias[128], s_g[128], s_b[128];

    const int tid = threadIdx.x;
    const int wid = tid >> 5, lane = tid & 31;
    const int grp = lane >> 2, tig = lane & 3;
    const int wm = wid & 3, wn = wid >> 2;
    const int tileM = blockIdx.x * 128;
    const int rBase = wm * 32;
    const int cBase = wn * 64;

    if (tid < 128) { s_bias[tid] = bias[tid]; s_g[tid] = gamma[tid]; s_b[tid] = beta[tid]; }

    float c[2][8][4];
#pragma unroll
    for (int mi = 0; mi < 2; mi++)
#pragma unroll
        for (int ni = 0; ni < 8; ni++)
#pragma unroll
            for (int j = 0; j < 4; j++) c[mi][ni][j] = 0.f;

    // per-thread fixed (row, 8-half chunk) slots: 512 slots per tile
    const int m0 = tid >> 2, p0 = (tid & 3) * 8;          // slots 0..255
    const int m1 = m0 + 64, p1 = p0;                      // slots 256..511

#define PREFETCH(CH)                                                           \
    {                                                                          \
        int ch_ = (CH);                                                        \
        if (ch_ < NCH) {                                                       \
            int buf_ = ch_ & 3;                                                \
            int k0_ = ch_ * 32;                                                \
            cp16(smem_u32(&sA[buf_][m0 * 40 + p0]),                            \
                 g_a + (size_t)(tileM + m0) * KT + k0_ + p0);                  \
            cp16(smem_u32(&sB[buf_][m0 * 40 + p0]),                            \
                 g_wt + (size_t)m0 * KT + k0_ + p0);                           \
            cp16(smem_u32(&sA[buf_][m1 * 40 + p1]),                            \
                 g_a + (size_t)(tileM + m1) * KT + k0_ + p1);                  \
            cp16(smem_u32(&sB[buf_][m1 * 40 + p1]),                            \
                 g_wt + (size_t)m1 * KT + k0_ + p1);                           \
        }                                                                      \
        asm volatile("cp.async.commit_group;" ::: "memory");                   \
    }

    PREFETCH(0); PREFETCH(1); PREFETCH(2);

    for (int ch = 0; ch < NCH; ch++) {
        const int buf = ch & 3;
        asm volatile("cp.async.wait_group 2;" ::: "memory");
        __syncthreads();
        PREFETCH(ch + 3);

#pragma unroll
        for (int ks = 0; ks < 2; ks++) {
            const int ko = ks * 16;
            uint32_t a[2][4];
#pragma unroll
            for (int mi = 0; mi < 2; mi++) {
                const unsigned short* pa =
                    &sA[buf][(rBase + mi * 16 + grp) * 40 + ko + tig * 2];
                a[mi][0] = *(const uint32_t*)pa;
                a[mi][1] = *(const uint32_t*)(pa + 8 * 40);
                a[mi][2] = *(const uint32_t*)(pa + 8);
                a[mi][3] = *(const uint32_t*)(pa + 8 * 40 + 8);
            }
            uint32_t b[8][2];
#pragma unroll
            for (int ni = 0; ni < 8; ni++) {
                const unsigned short* pb =
                    &sB[buf][(cBase + ni * 8 + grp) * 40 + ko + tig * 2];
                b[ni][0] = *(const uint32_t*)pb;
                b[ni][1] = *(const uint32_t*)(pb + 8);
            }
#pragma unroll
            for (int mi = 0; mi < 2; mi++)
#pragma unroll
                for (int ni = 0; ni < 8; ni++)
                    mma_f16(c[mi][ni], a[mi], b[ni]);
        }
    }
#undef PREFETCH
    __syncthreads();

    // ---- epilogue: bias, per-row LN stats, normalize, ReLU, store ----
#pragma unroll
    for (int ni = 0; ni < 8; ni++) {
        int col = cBase + ni * 8 + 2 * tig;
        float b0 = s_bias[col], b1 = s_bias[col + 1];
#pragma unroll
        for (int mi = 0; mi < 2; mi++) {
            c[mi][ni][0] += b0; c[mi][ni][1] += b1;
            c[mi][ni][2] += b0; c[mi][ni][3] += b1;
        }
    }
#pragma unroll
    for (int mi = 0; mi < 2; mi++)
#pragma unroll
        for (int h = 0; h < 2; h++) {
            float s = 0.f, ss = 0.f;
#pragma unroll
            for (int ni = 0; ni < 8; ni++) {
                float v0 = c[mi][ni][2 * h], v1 = c[mi][ni][2 * h + 1];
                s += v0 + v1;
                ss += v0 * v0 + v1 * v1;
            }
            s  += __shfl_xor_sync(0xffffffffu, s, 1);
            s  += __shfl_xor_sync(0xffffffffu, s, 2);
            ss += __shfl_xor_sync(0xffffffffu, ss, 1);
            ss += __shfl_xor_sync(0xffffffffu, ss, 2);
            if (tig == 0)
                sRow[wn][rBase + mi * 16 + h * 8 + grp] = make_float2(s, ss);
        }
    __syncthreads();

#pragma unroll
    for (int mi = 0; mi < 2; mi++)
#pragma unroll
        for (int h = 0; h < 2; h++) {
            int row = rBase + mi * 16 + h * 8 + grp;
            int gRow = tileM + row;
            if (gRow >= NN) continue;
            float2 p0v = sRow[0][row], p1v = sRow[1][row];
            float s = p0v.x + p1v.x, ss = p0v.y + p1v.y;
            float mean = s * (1.0f / DD);
            float var  = ss * (1.0f / DD) - mean * mean;
            float rstd = rsqrtf(var + LN_EPS);
#pragma unroll
            for (int ni = 0; ni < 8; ni++) {
                int col = cBase + ni * 8 + 2 * tig;
                float2 r;
                r.x = fmaxf((c[mi][ni][2 * h]     - mean) * rstd * s_g[col]     + s_b[col],     0.f);
                r.y = fmaxf((c[mi][ni][2 * h + 1] - mean) * rstd * s_g[col + 1] + s_b[col + 1], 0.f);
                *(float2*)(out + (size_t)gRow * DD + col) = r;
            }
        }
}

// ---------------------------------------------------------------------------
extern "C" void kernel_launch(void* const* d_in, const int* in_sizes, int n_in,
                              void* d_out, int out_size) {
    const float* x  = (const float*)d_in[0];
    const void*  ei = d_in[1];
    const void*  et = d_in[2];
    int base = 3;
    if (n_in > 3 && in_sizes[3] == 1) base = 4;
    const float* Wrel  = (const float*)d_in[base + 0];
    const float* Wroot = (const float*)d_in[base + 1];
    const float* bias  = (const float*)d_in[base + 2];
    const float* gamma = (const float*)d_in[base + 3];
    const float* beta  = (const float*)d_in[base + 4];
    float* out = (float*)d_out;

    k_init  <<<(NN * 32 + 255) / 256, 256>>>((const unsigned int*)ei,
                                             (const unsigned int*)et,
                                             x, Wrel, Wroot);
    k_sort  <<<(EE + 255) / 256, 256>>>(ei, et);
    k_gather<<<(NR * 32 + 255) / 256, 256>>>();
    k_mma_ln<<<NPAD / 128, 256>>>(bias, gamma, beta, out);
}

// round 14
// speedup vs baseline: 1.6889x; 1.0025x over previous
#include <cuda_runtime.h>
#include <cuda_fp16.h>
#include <cstdint>

// Problem constants
#define NN  50000
#define EE  1600000
#define DD  128
#define RR  8
#define NR  (NN*RR)      // 400000
#define KT  1152         // R*D + D
#define NPAD 50048       // 391 * 128
#define LN_EPS 1e-5f
#define NCH 36           // KT / 32
#define CAP 32           // fixed bucket capacity (P(overflow) ~ 4e-12)

// A in chunk-major layout: g_a2[tile][ch][row][32 halves]
//   tile = node>>7 (391), ch = kcol>>5 (36), row = node&127, off = kcol&31
//   -> per-(CTA, chunk) GEMM read = contiguous 8 KB
__device__ __align__(256) unsigned short g_a2[(size_t)NPAD * KT];
__device__ __align__(256) unsigned short g_wt[128 * KT];   // fp16 W^T [N=128,K]
__device__ __align__(256) unsigned short g_x16[NN * DD];   // fp16 copy of x
__device__ int g_cnt[NR];
__device__ unsigned short g_srt[(size_t)NR * CAP];         // 25.6 MB u16 bucket slots
__device__ int g_ei64, g_et64;

// ---------------------------------------------------------------------------
static __device__ __forceinline__ uint32_t smem_u32(const void* p) {
    uint32_t a;
    asm("{ .reg .u64 t; cvta.to.shared.u64 t, %1; cvt.u32.u64 %0, t; }"
        : "=r"(a) : "l"(p));
    return a;
}
static __device__ __forceinline__ void cp16(uint32_t dst, const void* src) {
    asm volatile("cp.async.cg.shared.global [%0], [%1], 16;"
                 :: "r"(dst), "l"(src) : "memory");
}
static __device__ __forceinline__ void st_cs_u2(void* p, uint32_t a, uint32_t b) {
    asm volatile("st.global.cs.v2.u32 [%0], {%1,%2};"
                 :: "l"(p), "r"(a), "r"(b) : "memory");
}
static __device__ __forceinline__ uint32_t h2u(__half2 h) {
    return *(uint32_t*)&h;
}
static __device__ __forceinline__ void mma_f16(float c[4], const uint32_t a[4],
                                               const uint32_t b[2]) {
    asm volatile(
        "mma.sync.aligned.m16n8k16.row.col.f32.f16.f16.f32 "
        "{%0,%1,%2,%3}, {%4,%5,%6,%7}, {%8,%9}, {%0,%1,%2,%3};"
        : "+f"(c[0]), "+f"(c[1]), "+f"(c[2]), "+f"(c[3])
        : "r"(a[0]), "r"(a[1]), "r"(a[2]), "r"(a[3]), "r"(b[0]), "r"(b[1]));
}
// A2 half-index for (node, kcol)
static __device__ __forceinline__ size_t a2_idx(int node, int kcol) {
    int tile = node >> 7, row = node & 127;
    int ch = kcol >> 5, off = kcol & 31;
    return (((size_t)tile * NCH + ch) << 12) + (row << 5) + off;
}

// ---------------------------------------------------------------------------
// k_init: zero counts + dtype detect (block 0) + fp16 x copy / A root slice +
// fp16 weight transpose.
// ---------------------------------------------------------------------------
__global__ void k_init(const unsigned int* __restrict__ ei_w,
                       const unsigned int* __restrict__ et_w,
                       const float* __restrict__ x,
                       const float* __restrict__ Wrel,
                       const float* __restrict__ Wroot) {
    int i = blockIdx.x * blockDim.x + threadIdx.x;

    if (blockIdx.x == 0) {                       // dtype detection
        __shared__ unsigned int a_ei, a_et;
        if (threadIdx.x == 0) { a_ei = 0u; a_et = 0u; }
        __syncthreads();
        unsigned int vei = 0u, vet = 0u;
#pragma unroll
        for (int j = 0; j < 8; j++) {
            int idx = threadIdx.x * 8 + j;
            vei |= ei_w[2 * idx + 1];
            vet |= et_w[2 * idx + 1];
        }
        atomicOr(&a_ei, vei);
        atomicOr(&a_et, vet);
        __syncthreads();
        if (threadIdx.x == 0) {
            g_ei64 = (a_ei == 0u) ? 1 : 0;
            g_et64 = (a_et == 0u) ? 1 : 0;
        }
    }
    if (i < NR) g_cnt[i] = 0;
    if (i < NN * 32) {                           // x -> fp16 + root slice of A2
        int node = i >> 5, c = (i & 31) * 4;
        float4 v = *(const float4*)(x + (size_t)node * DD + c);
        uint32_t u0 = h2u(__floats2half2_rn(v.x, v.y));
        uint32_t u1 = h2u(__floats2half2_rn(v.z, v.w));
        ((uint2*)g_x16)[i] = make_uint2(u0, u1);
        st_cs_u2(g_a2 + a2_idx(node, 1024 + c), u0, u1);
    }
    if (i < 128 * KT) {                          // W^T fp16
        int n = i & 127, k = i >> 7;
        float v = (k < 1024) ? Wrel[(size_t)k * 128 + n]
                             : Wroot[(size_t)(k - 1024) * 128 + n];
        g_wt[(size_t)n * KT + k] = __half_as_ushort(__float2half_rn(v));
    }
}

// ---------------------------------------------------------------------------
// k_sort: one pass over edges -> fixed-capacity u16 buckets.
// ---------------------------------------------------------------------------
__global__ void k_sort(const void* __restrict__ ei_v,
                       const void* __restrict__ et_v) {
    int e = blockIdx.x * blockDim.x + threadIdx.x;
    if (e >= EE) return;
    int s, d, r;
    if (g_ei64) {
        const long long* p = (const long long*)ei_v;
        s = (int)p[e];
        d = (int)p[EE + e];
    } else {
        const int* p = (const int*)ei_v;
        s = p[e];
        d = p[EE + e];
    }
    if (g_et64) r = (int)((const long long*)et_v)[e];
    else        r = ((const int*)et_v)[e];
    int key = d * RR + r;
    int pos = atomicAdd(&g_cnt[key], 1);
    if (pos < CAP) g_srt[(size_t)key * CAP + pos] = (unsigned short)s;
}

// ---------------------------------------------------------------------------
// One warp per (dst,rel) bucket: A2[node, rel*128+*] = fp16(mean of x16[src])
// ---------------------------------------------------------------------------
__global__ __launch_bounds__(256)
void k_gather() {
    int w = (blockIdx.x * blockDim.x + threadIdx.x) >> 5;
    if (w >= NR) return;
    int lane = threadIdx.x & 31;
    const unsigned short* bucket = g_srt + (size_t)w * CAP;
    int n = min(g_cnt[w], CAP);
    const uint2* xv = (const uint2*)g_x16;
    float4 acc = make_float4(0.f, 0.f, 0.f, 0.f);
    int j = 0;
    for (; j + 3 < n; j += 4) {
        int s0 = bucket[j];
        int s1 = bucket[j + 1];
        int s2 = bucket[j + 2];
        int s3 = bucket[j + 3];
        uint2 u0 = xv[s0 * 32 + lane];
        uint2 u1 = xv[s1 * 32 + lane];
        uint2 u2 = xv[s2 * 32 + lane];
        uint2 u3 = xv[s3 * 32 + lane];
        float2 a0 = __half22float2(*(__half2*)&u0.x), b0 = __half22float2(*(__half2*)&u0.y);
        float2 a1 = __half22float2(*(__half2*)&u1.x), b1 = __half22float2(*(__half2*)&u1.y);
        float2 a2 = __half22float2(*(__half2*)&u2.x), b2 = __half22float2(*(__half2*)&u2.y);
        float2 a3 = __half22float2(*(__half2*)&u3.x), b3 = __half22float2(*(__half2*)&u3.y);
        acc.x += (a0.x + a1.x) + (a2.x + a3.x);
        acc.y += (a0.y + a1.y) + (a2.y + a3.y);
        acc.z += (b0.x + b1.x) + (b2.x + b3.x);
        acc.w += (b0.y + b1.y) + (b2.y + b3.y);
    }
    for (; j < n; j++) {
        int s0 = bucket[j];
        uint2 u0 = xv[s0 * 32 + lane];
        float2 a0 = __half22float2(*(__half2*)&u0.x), b0 = __half22float2(*(__half2*)&u0.y);
        acc.x += a0.x; acc.y += a0.y; acc.z += b0.x; acc.w += b0.y;
    }
    float sc = 1.0f / fmaxf((float)n, 1.0f);
    uint32_t u0 = h2u(__floats2half2_rn(acc.x * sc, acc.y * sc));
    uint32_t u1 = h2u(__floats2half2_rn(acc.z * sc, acc.w * sc));
    int node = w >> 3, rel = w & 7;
    st_cs_u2(g_a2 + a2_idx(node, rel * 128 + lane * 4), u0, u1);
}

// ---------------------------------------------------------------------------
// fp16 mma.sync GEMM (M=128/CTA, N=128, K=1152) + bias + LN + ReLU.
// 8 warps 4x2; warp tile 32x64; BK=32 (36 chunks). 4-stage cp.async.
// A now read as contiguous 8 KB blocks per (CTA, chunk) -> DRAM streaming.
// ---------------------------------------------------------------------------
__global__ void __launch_bounds__(256, 2)
k_mma_ln(const float* __restrict__ bias, const float* __restrict__ gamma,
         const float* __restrict__ beta, float* __restrict__ out) {
    __shared__ unsigned short sA[4][128 * 40];   // 40.96 KB
    __shared__ unsigned short sB[4][128 * 40];   // 40.96 KB
    __shared__ float2 sRow[2][128];
    __shared__ float s_bias[128], s_g[128], s_b[128];

    const int tid = threadIdx.x;
    const int wid = tid >> 5, lane = tid & 31;
    const int grp = lane >> 2, tig = lane & 3;
    const int wm = wid & 3, wn = wid >> 2;
    const int tileM = blockIdx.x * 128;
    const int rBase = wm * 32;
    const int cBase = wn * 64;

    if (tid < 128) { s_bias[tid] = bias[tid]; s_g[tid] = gamma[tid]; s_b[tid] = beta[tid]; }

    float c[2][8][4];
#pragma unroll
    for (int mi = 0; mi < 2; mi++)
#pragma unroll
        for (int ni = 0; ni < 8; ni++)
#pragma unroll
            for (int j = 0; j < 4; j++) c[mi][ni][j] = 0.f;

    // per-thread fixed (row, 8-half chunk) slots: 512 slots per tile
    const int m0 = tid >> 2, p0 = (tid & 3) * 8;          // rows 0..63
    const int m1 = m0 + 64, p1 = p0;                      // rows 64..127
    const unsigned short* aBase = g_a2 + (((size_t)blockIdx.x * NCH) << 12);

#define PREFETCH(CH)                                                           \
    {                                                                          \
        int ch_ = (CH);                                                        \
        if (ch_ < NCH) {                                                       \
            int buf_ = ch_ & 3;                                                \
            const unsigned short* aSrc = aBase + ((size_t)ch_ << 12);          \
            int k0_ = ch_ * 32;                                                \
            cp16(smem_u32(&sA[buf_][m0 * 40 + p0]), aSrc + m0 * 32 + p0);      \
            cp16(smem_u32(&sB[buf_][m0 * 40 + p0]),                            \
                 g_wt + (size_t)m0 * KT + k0_ + p0);                           \
            cp16(smem_u32(&sA[buf_][m1 * 40 + p1]), aSrc + m1 * 32 + p1);      \
            cp16(smem_u32(&sB[buf_][m1 * 40 + p1]),                            \
                 g_wt + (size_t)m1 * KT + k0_ + p1);                           \
        }                                                                      \
        asm volatile("cp.async.commit_group;" ::: "memory");                   \
    }

    PREFETCH(0); PREFETCH(1); PREFETCH(2);

    for (int ch = 0; ch < NCH; ch++) {
        const int buf = ch & 3;
        asm volatile("cp.async.wait_group 2;" ::: "memory");
        __syncthreads();
        PREFETCH(ch + 3);

#pragma unroll
        for (int ks = 0; ks < 2; ks++) {
            const int ko = ks * 16;
            uint32_t a[2][4];
#pragma unroll
            for (int mi = 0; mi < 2; mi++) {
                const unsigned short* pa =
                    &sA[buf][(rBase + mi * 16 + grp) * 40 + ko + tig * 2];
                a[mi][0] = *(const uint32_t*)pa;
                a[mi][1] = *(const uint32_t*)(pa + 8 * 40);
                a[mi][2] = *(const uint32_t*)(pa + 8);
                a[mi][3] = *(const uint32_t*)(pa + 8 * 40 + 8);
            }
            uint32_t b[8][2];
#pragma unroll
            for (int ni = 0; ni < 8; ni++) {
                const unsigned short* pb =
                    &sB[buf][(cBase + ni * 8 + grp) * 40 + ko + tig * 2];
                b[ni][0] = *(const uint32_t*)pb;
                b[ni][1] = *(const uint32_t*)(pb + 8);
            }
#pragma unroll
            for (int mi = 0; mi < 2; mi++)
#pragma unroll
                for (int ni = 0; ni < 8; ni++)
                    mma_f16(c[mi][ni], a[mi], b[ni]);
        }
    }
#undef PREFETCH
    __syncthreads();

    // ---- epilogue: bias, per-row LN stats, normalize, ReLU, store ----
#pragma unroll
    for (int ni = 0; ni < 8; ni++) {
        int col = cBase + ni * 8 + 2 * tig;
        float b0 = s_bias[col], b1 = s_bias[col + 1];
#pragma unroll
        for (int mi = 0; mi < 2; mi++) {
            c[mi][ni][0] += b0; c[mi][ni][1] += b1;
            c[mi][ni][2] += b0; c[mi][ni][3] += b1;
        }
    }
#pragma unroll
    for (int mi = 0; mi < 2; mi++)
#pragma unroll
        for (int h = 0; h < 2; h++) {
            float s = 0.f, ss = 0.f;
#pragma unroll
            for (int ni = 0; ni < 8; ni++) {
                float v0 = c[mi][ni][2 * h], v1 = c[mi][ni][2 * h + 1];
                s += v0 + v1;
                ss += v0 * v0 + v1 * v1;
            }
            s  += __shfl_xor_sync(0xffffffffu, s, 1);
            s  += __shfl_xor_sync(0xffffffffu, s, 2);
            ss += __shfl_xor_sync(0xffffffffu, ss, 1);
            ss += __shfl_xor_sync(0xffffffffu, ss, 2);
            if (tig == 0)
                sRow[wn][rBase + mi * 16 + h * 8 + grp] = make_float2(s, ss);
        }
    __syncthreads();

#pragma unroll
    for (int mi = 0; mi < 2; mi++)
#pragma unroll
        for (int h = 0; h < 2; h++) {
            int row = rBase + mi * 16 + h * 8 + grp;
            int gRow = tileM + row;
            if (gRow >= NN) continue;
            float2 p0v = sRow[0][row], p1v = sRow[1][row];
            float s = p0v.x + p1v.x, ss = p0v.y + p1v.y;
            float mean = s * (1.0f / DD);
            float var  = ss * (1.0f / DD) - mean * mean;
            float rstd = rsqrtf(var + LN_EPS);
#pragma unroll
            for (int ni = 0; ni < 8; ni++) {
                int col = cBase + ni * 8 + 2 * tig;
                float2 r;
                r.x = fmaxf((c[mi][ni][2 * h]     - mean) * rstd * s_g[col]     + s_b[col],     0.f);
                r.y = fmaxf((c[mi][ni][2 * h + 1] - mean) * rstd * s_g[col + 1] + s_b[col + 1], 0.f);
                *(float2*)(out + (size_t)gRow * DD + col) = r;
            }
        }
}

// ---------------------------------------------------------------------------
extern "C" void kernel_launch(void* const* d_in, const int* in_sizes, int n_in,
                              void* d_out, int out_size) {
    const float* x  = (const float*)d_in[0];
    const void*  ei = d_in[1];
    const void*  et = d_in[2];
    int base = 3;
    if (n_in > 3 && in_sizes[3] == 1) base = 4;
    const float* Wrel  = (const float*)d_in[base + 0];
    const float* Wroot = (const float*)d_in[base + 1];
    const float* bias  = (const float*)d_in[base + 2];
    const float* gamma = (const float*)d_in[base + 3];
    const float* beta  = (const float*)d_in[base + 4];
    float* out = (float*)d_out;

    k_init  <<<(NN * 32 + 255) / 256, 256>>>((const unsigned int*)ei,
                                             (const unsigned int*)et,
                                             x, Wrel, Wroot);
    k_sort  <<<(EE + 255) / 256, 256>>>(ei, et);
    k_gather<<<(NR * 32 + 255) / 256, 256>>>();
    k_mma_ln<<<NPAD / 128, 256>>>(bias, gamma, beta, out);
}